// round 13
// baseline (speedup 1.0000x reference)
#include <cuda_runtime.h>
#include <math.h>

#define HH 512
#define WW 512
#define HWSZ (HH * WW)
#define NTHREADS 512
#define NWARPS 16
#define EPSV 1e-8f

#define MAXPLANES 256
#define STRIDE_ST 2052            // rowM[512] rowI[512] colM[512] colI[512] insM insI
#define STAGE_ROWS 48
#define STAGE_BYTES (STAGE_ROWS * WW * 4)    // 96 KB dynamic smem
#define DYNROW0 STAGE_ROWS
#define BANDROWS 16
#define BANDS ((HH - STAGE_ROWS) / BANDROWS) // 29 dynamic bands per plane

__device__ float g_stats[MAXPLANES * STRIDE_ST];
__device__ unsigned int g_counter;
__device__ int g_flag[MAXPLANES];

__global__ void init_kernel() {
    if (threadIdx.x == 0) g_counter = 0u;
    if (threadIdx.x < MAXPLANES) g_flag[threadIdx.x] = 0;
}

__global__ __launch_bounds__(NTHREADS, 2) void ircn_fused(
    const float* __restrict__ in,
    const float* __restrict__ gRow_p, const float* __restrict__ bRow_p,
    const float* __restrict__ gCol_p, const float* __restrict__ bCol_p,
    const float* __restrict__ gIns_p, const float* __restrict__ bIns_p,
    float* __restrict__ out, int C, int nPlanes)
{
    extern __shared__ __align__(16) float4 stage4[];   // STAGE_ROWS x 128 float4

    __shared__ __align__(16) float rowS[HH];    // raw sums -> (mean, inv)
    __shared__ __align__(16) float rowSS[HH];
    __shared__ __align__(16) float colS[WW];    // phase A: own col stats; B2: unit's colM/colI
    __shared__ __align__(16) float colSS[WW];
    __shared__ float warpRed[NWARPS * 2];
    __shared__ float sIns[2];
    __shared__ float sRowM[BANDROWS];
    __shared__ float sRowI[BANDROWS];
    __shared__ float sP[8];
    __shared__ unsigned int sU;

    const int plane = blockIdx.x;               // this CTA's owned plane
    const int c = plane % C;
    const int b = plane / C;
    const float* __restrict__ p = in + (size_t)plane * HWSZ;

    const int tid = threadIdx.x;
    const int lane = tid & 31;
    const int wid = tid >> 5;

    colS[tid] = 0.f;
    colSS[tid] = 0.f;
    __syncthreads();

    // ================= Phase A: read plane once, stats + stage head rows ========
    float cs[16], css[16];
#pragma unroll
    for (int i = 0; i < 16; i++) { cs[i] = 0.f; css[i] = 0.f; }

    for (int r = wid; r < HH; r += NWARPS) {
        const float4* rp = (const float4*)(p + (size_t)r * WW);
        float4 v[4];
#pragma unroll
        for (int k = 0; k < 4; k++) v[k] = __ldcg(&rp[k * 32 + lane]);

        if (r < STAGE_ROWS) {
#pragma unroll
            for (int k = 0; k < 4; k++) stage4[r * 128 + k * 32 + lane] = v[k];
        }

        float s = 0.f, ss = 0.f;
#pragma unroll
        for (int k = 0; k < 4; k++) {
            s += (v[k].x + v[k].y) + (v[k].z + v[k].w);
            ss += v[k].x * v[k].x + v[k].y * v[k].y + v[k].z * v[k].z + v[k].w * v[k].w;
            cs[k * 4 + 0] += v[k].x;  css[k * 4 + 0] += v[k].x * v[k].x;
            cs[k * 4 + 1] += v[k].y;  css[k * 4 + 1] += v[k].y * v[k].y;
            cs[k * 4 + 2] += v[k].z;  css[k * 4 + 2] += v[k].z * v[k].z;
            cs[k * 4 + 3] += v[k].w;  css[k * 4 + 3] += v[k].w * v[k].w;
        }
#pragma unroll
        for (int o = 16; o > 0; o >>= 1) {
            s += __shfl_xor_sync(0xffffffffu, s, o);
            ss += __shfl_xor_sync(0xffffffffu, ss, o);
        }
        if (lane == 0) { rowS[r] = s; rowSS[r] = ss; }
    }

#pragma unroll
    for (int k = 0; k < 4; k++) {
        int cbase = (k * 32 + lane) * 4;
#pragma unroll
        for (int j = 0; j < 4; j++) {
            atomicAdd(&colS[cbase + j], cs[k * 4 + j]);
            atomicAdd(&colSS[cbase + j], css[k * 4 + j]);
        }
    }
    __syncthreads();

    // instance reduction from row sums
    {
        float s = rowS[tid], ss = rowSS[tid];
#pragma unroll
        for (int o = 16; o > 0; o >>= 1) {
            s += __shfl_xor_sync(0xffffffffu, s, o);
            ss += __shfl_xor_sync(0xffffffffu, ss, o);
        }
        if (lane == 0) { warpRed[wid] = s; warpRed[NWARPS + wid] = ss; }
    }
    __syncthreads();
    if (tid == 0) {
        float s = 0.f, ss = 0.f;
        for (int i = 0; i < NWARPS; i++) { s += warpRed[i]; ss += warpRed[NWARPS + i]; }
        float m = s * (1.f / HWSZ);
        float v = fmaxf(ss * (1.f / HWSZ) - m * m, 0.f);
        sIns[0] = m;
        sIns[1] = 1.f / (sqrtf(v + EPSV) + EPSV);
    }

    // raw sums -> (mean, inv); thread t owns index t
    {
        float m = rowS[tid] * (1.f / WW);
        float v = fmaxf(rowSS[tid] * (1.f / WW) - m * m, 0.f);
        rowS[tid] = m;
        rowSS[tid] = 1.f / (sqrtf(v + EPSV) + EPSV);

        float mc = colS[tid] * (1.f / HH);
        float vc = fmaxf(colSS[tid] * (1.f / HH) - mc * mc, 0.f);
        colS[tid] = mc;
        colSS[tid] = 1.f / (sqrtf(vc + EPSV) + EPSV);
    }
    __syncthreads();

    // ================= Publish stats (release) ================================
    {
        float* st = g_stats + (size_t)plane * STRIDE_ST;
        st[tid]        = rowS[tid];
        st[512 + tid]  = rowSS[tid];
        st[1024 + tid] = colS[tid];
        st[1536 + tid] = colSS[tid];
        if (tid == 0) { st[2048] = sIns[0]; st[2049] = sIns[1]; }
    }
    __syncthreads();
    if (tid == 0) {
        __threadfence();
        atomicExch(&g_flag[plane], 1);
    }

    // ================= Phase B1: staged head rows from smem ===================
    const float gRow = gRow_p[c], bRow = bRow_p[c];
    const float gCol = gCol_p[c], bCol = bCol_p[c];
    const float gIns = gIns_p[c], bIns = bIns_p[c];
    const float insM = sIns[0], insI = sIns[1];

    {
        const size_t outBase = (size_t)b * 3 * C * HWSZ;
        float* __restrict__ oI = out + outBase + (size_t)c * HWSZ;
        float* __restrict__ oR = out + outBase + (size_t)(C + c) * HWSZ;
        float* __restrict__ oC = out + outBase + (size_t)(2 * C + c) * HWSZ;
        const float4* colM4 = (const float4*)colS;
        const float4* colI4 = (const float4*)colSS;

        for (int r = wid; r < STAGE_ROWS; r += NWARPS) {
            float4* oIp = (float4*)(oI + (size_t)r * WW);
            float4* oRp = (float4*)(oR + (size_t)r * WW);
            float4* oCp = (float4*)(oC + (size_t)r * WW);
            const float rm = rowS[r];
            const float ri = rowSS[r];
#pragma unroll
            for (int k = 0; k < 4; k++) {
                const int idx = k * 32 + lane;
                float4 v = stage4[r * 128 + idx];
                float4 cm = colM4[idx];
                float4 ci = colI4[idx];
                float4 o;
                o.x = gIns * (v.x - insM) * insI + bIns;
                o.y = gIns * (v.y - insM) * insI + bIns;
                o.z = gIns * (v.z - insM) * insI + bIns;
                o.w = gIns * (v.w - insM) * insI + bIns;
                __stcs(&oIp[idx], o);
                o.x = gRow * (v.x - rm) * ri + bRow;
                o.y = gRow * (v.y - rm) * ri + bRow;
                o.z = gRow * (v.z - rm) * ri + bRow;
                o.w = gRow * (v.w - rm) * ri + bRow;
                __stcs(&oRp[idx], o);
                o.x = gCol * (v.x - cm.x) * ci.x + bCol;
                o.y = gCol * (v.y - cm.y) * ci.y + bCol;
                o.z = gCol * (v.z - cm.z) * ci.z + bCol;
                o.w = gCol * (v.w - cm.w) * ci.w + bCol;
                __stcs(&oCp[idx], o);
            }
        }
    }

    // ================= Phase B2: dynamic 16-row bands =========================
    // Forward plane order (low planes publish first -> near-zero spin),
    // reverse band order within a plane (tail rows are the L2-warm ones).
    const unsigned int nUnits = (unsigned int)(nPlanes * BANDS);

    for (;;) {
        if (tid == 0) sU = atomicAdd(&g_counter, 1u);
        __syncthreads();                       // also: all threads done with prev smem use
        const unsigned int u = sU;
        if (u >= nUnits) break;

        const int p2 = (int)(u / BANDS);
        const int band = (BANDS - 1) - (int)(u % BANDS);
        const int row0 = DYNROW0 + band * BANDROWS;
        const float* __restrict__ st = g_stats + (size_t)p2 * STRIDE_ST;

        if (tid == 0) {
            while (atomicAdd(&g_flag[p2], 0) == 0) __nanosleep(64);
            __threadfence();
        }
        __syncthreads();

        // stage this unit's stats in smem (reuse phase-A arrays)
        colS[tid]  = st[1024 + tid];           // colM
        colSS[tid] = st[1536 + tid];           // colI
        if (tid < BANDROWS) {
            sRowM[tid] = st[row0 + tid];
            sRowI[tid] = st[512 + row0 + tid];
        }
        if (tid == 0) {
            const int c2 = p2 % C;
            sP[0] = st[2048];   sP[1] = st[2049];
            sP[2] = gRow_p[c2]; sP[3] = bRow_p[c2];
            sP[4] = gCol_p[c2]; sP[5] = bCol_p[c2];
            sP[6] = gIns_p[c2]; sP[7] = bIns_p[c2];
        }
        __syncthreads();

        const int c2 = p2 % C;
        const int b2 = p2 / C;
        const float iM = sP[0], iI = sP[1];
        const float gR = sP[2], bR = sP[3];
        const float gC = sP[4], bC = sP[5];
        const float gI = sP[6], bI = sP[7];

        const size_t outBase = (size_t)b2 * 3 * C * HWSZ;
        float* __restrict__ oI = out + outBase + (size_t)c2 * HWSZ;
        float* __restrict__ oR = out + outBase + (size_t)(C + c2) * HWSZ;
        float* __restrict__ oC = out + outBase + (size_t)(2 * C + c2) * HWSZ;
        const float* __restrict__ p2p = in + (size_t)p2 * HWSZ;

        const float4* colM4 = (const float4*)colS;
        const float4* colI4 = (const float4*)colSS;

        {
            const int r = row0 + wid;          // 16 warps x 1 row = 16-row band
            const float4* rp = (const float4*)(p2p + (size_t)r * WW);
            float4* oIp = (float4*)(oI + (size_t)r * WW);
            float4* oRp = (float4*)(oR + (size_t)r * WW);
            float4* oCp = (float4*)(oC + (size_t)r * WW);
            const float rm = sRowM[wid];
            const float ri = sRowI[wid];
#pragma unroll
            for (int k = 0; k < 4; k++) {
                const int idx = k * 32 + lane;
                float4 v = __ldcs(&rp[idx]);
                float4 cm = colM4[idx];
                float4 ci = colI4[idx];
                float4 o;
                o.x = gI * (v.x - iM) * iI + bI;
                o.y = gI * (v.y - iM) * iI + bI;
                o.z = gI * (v.z - iM) * iI + bI;
                o.w = gI * (v.w - iM) * iI + bI;
                __stcs(&oIp[idx], o);
                o.x = gR * (v.x - rm) * ri + bR;
                o.y = gR * (v.y - rm) * ri + bR;
                o.z = gR * (v.z - rm) * ri + bR;
                o.w = gR * (v.w - rm) * ri + bR;
                __stcs(&oRp[idx], o);
                o.x = gC * (v.x - cm.x) * ci.x + bC;
                o.y = gC * (v.y - cm.y) * ci.y + bC;
                o.z = gC * (v.z - cm.z) * ci.z + bC;
                o.w = gC * (v.w - cm.w) * ci.w + bC;
                __stcs(&oCp[idx], o);
            }
        }
    }
}

extern "C" void kernel_launch(void* const* d_in, const int* in_sizes, int n_in,
                              void* d_out, int out_size) {
    const float* in = (const float*)d_in[0];
    const float* gRow = (const float*)d_in[1];
    const float* bRow = (const float*)d_in[2];
    const float* gCol = (const float*)d_in[3];
    const float* bCol = (const float*)d_in[4];
    const float* gIns = (const float*)d_in[5];
    const float* bIns = (const float*)d_in[6];
    float* out = (float*)d_out;

    const int C = in_sizes[1];                  // 128
    const int nPlanes = in_sizes[0] / HWSZ;     // B*C = 256

    cudaFuncSetAttribute(ircn_fused,
                         cudaFuncAttributeMaxDynamicSharedMemorySize, STAGE_BYTES);

    init_kernel<<<1, 256>>>();
    ircn_fused<<<nPlanes, NTHREADS, STAGE_BYTES>>>(
        in, gRow, bRow, gCol, bCol, gIns, bIns, out, C, nPlanes);
}

// round 14
// speedup vs baseline: 1.0108x; 1.0108x over previous
#include <cuda_runtime.h>
#include <math.h>

#define HH 512
#define WW 512
#define HWSZ (HH * WW)
#define NTHREADS 512
#define NWARPS 16
#define EPSV 1e-8f

#define MAXPLANES 256
#define STRIDE_ST 2052            // rowM[512] rowI[512] colM[512] colI[512] insM insI
#define STAGE_ROWS 48
#define STAGE_BYTES (STAGE_ROWS * WW * 4)    // 96 KB dynamic smem
#define DYNROW0 STAGE_ROWS
#define BANDROWS 16
#define BANDS ((HH - STAGE_ROWS) / BANDROWS) // 29 dynamic bands per plane

__device__ float g_stats[MAXPLANES * STRIDE_ST];
__device__ unsigned int g_counter;   // consumer cursor over units
__device__ unsigned int g_pub;       // publisher slot cursor
__device__ int g_ready[MAXPLANES];   // slot -> plane+1 (0 = not yet published)

__global__ void init_kernel() {
    if (threadIdx.x == 0) { g_counter = 0u; g_pub = 0u; }
    if (threadIdx.x < MAXPLANES) g_ready[threadIdx.x] = 0;
}

__global__ __launch_bounds__(NTHREADS, 2) void ircn_fused(
    const float* __restrict__ in,
    const float* __restrict__ gRow_p, const float* __restrict__ bRow_p,
    const float* __restrict__ gCol_p, const float* __restrict__ bCol_p,
    const float* __restrict__ gIns_p, const float* __restrict__ bIns_p,
    float* __restrict__ out, int C, int nPlanes)
{
    extern __shared__ __align__(16) float4 stage4[];   // STAGE_ROWS x 128 float4

    __shared__ __align__(16) float rowS[HH];
    __shared__ __align__(16) float rowSS[HH];
    __shared__ __align__(16) float colS[WW];    // A: own col stats; B2: unit's colM/colI
    __shared__ __align__(16) float colSS[WW];
    __shared__ float warpRed[NWARPS * 2];
    __shared__ float sIns[2];
    __shared__ float sRowM[BANDROWS];
    __shared__ float sRowI[BANDROWS];
    __shared__ float sP[8];
    __shared__ unsigned int sU;
    __shared__ int sPlane;

    const int plane = blockIdx.x;               // this CTA's owned plane
    const int c = plane % C;
    const int b = plane / C;
    const float* __restrict__ p = in + (size_t)plane * HWSZ;

    const int tid = threadIdx.x;
    const int lane = tid & 31;
    const int wid = tid >> 5;

    colS[tid] = 0.f;
    colSS[tid] = 0.f;
    __syncthreads();

    // ================= Phase A: read plane once, stats + stage head rows ========
    float cs[16], css[16];
#pragma unroll
    for (int i = 0; i < 16; i++) { cs[i] = 0.f; css[i] = 0.f; }

    for (int r = wid; r < HH; r += NWARPS) {
        const float4* rp = (const float4*)(p + (size_t)r * WW);
        float4 v[4];
#pragma unroll
        for (int k = 0; k < 4; k++) v[k] = __ldcg(&rp[k * 32 + lane]);

        if (r < STAGE_ROWS) {
#pragma unroll
            for (int k = 0; k < 4; k++) stage4[r * 128 + k * 32 + lane] = v[k];
        }

        float s = 0.f, ss = 0.f;
#pragma unroll
        for (int k = 0; k < 4; k++) {
            s += (v[k].x + v[k].y) + (v[k].z + v[k].w);
            ss += v[k].x * v[k].x + v[k].y * v[k].y + v[k].z * v[k].z + v[k].w * v[k].w;
            cs[k * 4 + 0] += v[k].x;  css[k * 4 + 0] += v[k].x * v[k].x;
            cs[k * 4 + 1] += v[k].y;  css[k * 4 + 1] += v[k].y * v[k].y;
            cs[k * 4 + 2] += v[k].z;  css[k * 4 + 2] += v[k].z * v[k].z;
            cs[k * 4 + 3] += v[k].w;  css[k * 4 + 3] += v[k].w * v[k].w;
        }
#pragma unroll
        for (int o = 16; o > 0; o >>= 1) {
            s += __shfl_xor_sync(0xffffffffu, s, o);
            ss += __shfl_xor_sync(0xffffffffu, ss, o);
        }
        if (lane == 0) { rowS[r] = s; rowSS[r] = ss; }
    }

#pragma unroll
    for (int k = 0; k < 4; k++) {
        int cbase = (k * 32 + lane) * 4;
#pragma unroll
        for (int j = 0; j < 4; j++) {
            atomicAdd(&colS[cbase + j], cs[k * 4 + j]);
            atomicAdd(&colSS[cbase + j], css[k * 4 + j]);
        }
    }
    __syncthreads();

    // instance reduction from row sums
    {
        float s = rowS[tid], ss = rowSS[tid];
#pragma unroll
        for (int o = 16; o > 0; o >>= 1) {
            s += __shfl_xor_sync(0xffffffffu, s, o);
            ss += __shfl_xor_sync(0xffffffffu, ss, o);
        }
        if (lane == 0) { warpRed[wid] = s; warpRed[NWARPS + wid] = ss; }
    }
    __syncthreads();
    if (tid == 0) {
        float s = 0.f, ss = 0.f;
        for (int i = 0; i < NWARPS; i++) { s += warpRed[i]; ss += warpRed[NWARPS + i]; }
        float m = s * (1.f / HWSZ);
        float v = fmaxf(ss * (1.f / HWSZ) - m * m, 0.f);
        sIns[0] = m;
        sIns[1] = 1.f / (sqrtf(v + EPSV) + EPSV);
    }

    // raw sums -> (mean, inv); thread t owns index t
    {
        float m = rowS[tid] * (1.f / WW);
        float v = fmaxf(rowSS[tid] * (1.f / WW) - m * m, 0.f);
        rowS[tid] = m;
        rowSS[tid] = 1.f / (sqrtf(v + EPSV) + EPSV);

        float mc = colS[tid] * (1.f / HH);
        float vc = fmaxf(colSS[tid] * (1.f / HH) - mc * mc, 0.f);
        colS[tid] = mc;
        colSS[tid] = 1.f / (sqrtf(vc + EPSV) + EPSV);
    }
    __syncthreads();

    // ================= Publish stats -> publication-order ready queue ==========
    {
        float* st = g_stats + (size_t)plane * STRIDE_ST;
        st[tid]        = rowS[tid];
        st[512 + tid]  = rowSS[tid];
        st[1024 + tid] = colS[tid];
        st[1536 + tid] = colSS[tid];
        if (tid == 0) { st[2048] = sIns[0]; st[2049] = sIns[1]; }
    }
    __syncthreads();
    if (tid == 0) {
        __threadfence();
        unsigned int slot = atomicAdd(&g_pub, 1u);
        atomicExch(&g_ready[slot], plane + 1);      // release: bands of this plane
    }

    // ================= Phase B1: staged head rows from smem ===================
    const float gRow = gRow_p[c], bRow = bRow_p[c];
    const float gCol = gCol_p[c], bCol = bCol_p[c];
    const float gIns = gIns_p[c], bIns = bIns_p[c];
    const float insM = sIns[0], insI = sIns[1];

    {
        const size_t outBase = (size_t)b * 3 * C * HWSZ;
        float* __restrict__ oI = out + outBase + (size_t)c * HWSZ;
        float* __restrict__ oR = out + outBase + (size_t)(C + c) * HWSZ;
        float* __restrict__ oC = out + outBase + (size_t)(2 * C + c) * HWSZ;
        const float4* colM4 = (const float4*)colS;
        const float4* colI4 = (const float4*)colSS;

        for (int r = wid; r < STAGE_ROWS; r += NWARPS) {
            float4* oIp = (float4*)(oI + (size_t)r * WW);
            float4* oRp = (float4*)(oR + (size_t)r * WW);
            float4* oCp = (float4*)(oC + (size_t)r * WW);
            const float rm = rowS[r];
            const float ri = rowSS[r];
#pragma unroll
            for (int k = 0; k < 4; k++) {
                const int idx = k * 32 + lane;
                float4 v = stage4[r * 128 + idx];
                float4 cm = colM4[idx];
                float4 ci = colI4[idx];
                float4 o;
                o.x = gIns * (v.x - insM) * insI + bIns;
                o.y = gIns * (v.y - insM) * insI + bIns;
                o.z = gIns * (v.z - insM) * insI + bIns;
                o.w = gIns * (v.w - insM) * insI + bIns;
                __stcs(&oIp[idx], o);
                o.x = gRow * (v.x - rm) * ri + bRow;
                o.y = gRow * (v.y - rm) * ri + bRow;
                o.z = gRow * (v.z - rm) * ri + bRow;
                o.w = gRow * (v.w - rm) * ri + bRow;
                __stcs(&oRp[idx], o);
                o.x = gCol * (v.x - cm.x) * ci.x + bCol;
                o.y = gCol * (v.y - cm.y) * ci.y + bCol;
                o.z = gCol * (v.z - cm.z) * ci.z + bCol;
                o.w = gCol * (v.w - cm.w) * ci.w + bCol;
                __stcs(&oCp[idx], o);
            }
        }
    }

    // ================= Phase B2: dynamic bands in PUBLICATION order ===========
    // Unit u -> ready-queue slot u/BANDS (popper waits only if that slot has not
    // been published yet == global work genuinely exhausted). Reverse band order
    // within a plane: tail rows are the most recently read -> L2-warm.
    const unsigned int nUnits = (unsigned int)(nPlanes * BANDS);

    for (;;) {
        if (tid == 0) sU = atomicAdd(&g_counter, 1u);
        __syncthreads();                       // also closes prev-iter smem reads
        const unsigned int u = sU;
        if (u >= nUnits) break;

        const unsigned int slot = u / BANDS;
        const int band = (BANDS - 1) - (int)(u % BANDS);
        const int row0 = DYNROW0 + band * BANDROWS;

        if (tid == 0) {
            int pl;
            while ((pl = atomicAdd(&g_ready[slot], 0)) == 0) __nanosleep(64);
            __threadfence();
            sPlane = pl - 1;
        }
        __syncthreads();
        const int p2 = sPlane;
        const float* __restrict__ st = g_stats + (size_t)p2 * STRIDE_ST;

        colS[tid]  = st[1024 + tid];           // colM
        colSS[tid] = st[1536 + tid];           // colI
        if (tid < BANDROWS) {
            sRowM[tid] = st[row0 + tid];
            sRowI[tid] = st[512 + row0 + tid];
        }
        if (tid == 0) {
            const int c2 = p2 % C;
            sP[0] = st[2048];   sP[1] = st[2049];
            sP[2] = gRow_p[c2]; sP[3] = bRow_p[c2];
            sP[4] = gCol_p[c2]; sP[5] = bCol_p[c2];
            sP[6] = gIns_p[c2]; sP[7] = bIns_p[c2];
        }
        __syncthreads();

        const int c2 = p2 % C;
        const int b2 = p2 / C;
        const float iM = sP[0], iI = sP[1];
        const float gR = sP[2], bR = sP[3];
        const float gC = sP[4], bC = sP[5];
        const float gI = sP[6], bI = sP[7];

        const size_t outBase = (size_t)b2 * 3 * C * HWSZ;
        float* __restrict__ oI = out + outBase + (size_t)c2 * HWSZ;
        float* __restrict__ oR = out + outBase + (size_t)(C + c2) * HWSZ;
        float* __restrict__ oC = out + outBase + (size_t)(2 * C + c2) * HWSZ;
        const float* __restrict__ p2p = in + (size_t)p2 * HWSZ;

        const float4* colM4 = (const float4*)colS;
        const float4* colI4 = (const float4*)colSS;

        {
            const int r = row0 + wid;          // 16 warps x 1 row = 16-row band
            const float4* rp = (const float4*)(p2p + (size_t)r * WW);
            float4* oIp = (float4*)(oI + (size_t)r * WW);
            float4* oRp = (float4*)(oR + (size_t)r * WW);
            float4* oCp = (float4*)(oC + (size_t)r * WW);
            const float rm = sRowM[wid];
            const float ri = sRowI[wid];
#pragma unroll
            for (int k = 0; k < 4; k++) {
                const int idx = k * 32 + lane;
                float4 v = __ldcs(&rp[idx]);
                float4 cm = colM4[idx];
                float4 ci = colI4[idx];
                float4 o;
                o.x = gI * (v.x - iM) * iI + bI;
                o.y = gI * (v.y - iM) * iI + bI;
                o.z = gI * (v.z - iM) * iI + bI;
                o.w = gI * (v.w - iM) * iI + bI;
                __stcs(&oIp[idx], o);
                o.x = gR * (v.x - rm) * ri + bR;
                o.y = gR * (v.y - rm) * ri + bR;
                o.z = gR * (v.z - rm) * ri + bR;
                o.w = gR * (v.w - rm) * ri + bR;
                __stcs(&oRp[idx], o);
                o.x = gC * (v.x - cm.x) * ci.x + bC;
                o.y = gC * (v.y - cm.y) * ci.y + bC;
                o.z = gC * (v.z - cm.z) * ci.z + bC;
                o.w = gC * (v.w - cm.w) * ci.w + bC;
                __stcs(&oCp[idx], o);
            }
        }
    }
}

extern "C" void kernel_launch(void* const* d_in, const int* in_sizes, int n_in,
                              void* d_out, int out_size) {
    const float* in = (const float*)d_in[0];
    const float* gRow = (const float*)d_in[1];
    const float* bRow = (const float*)d_in[2];
    const float* gCol = (const float*)d_in[3];
    const float* bCol = (const float*)d_in[4];
    const float* gIns = (const float*)d_in[5];
    const float* bIns = (const float*)d_in[6];
    float* out = (float*)d_out;

    const int C = in_sizes[1];                  // 128
    const int nPlanes = in_sizes[0] / HWSZ;     // B*C = 256

    cudaFuncSetAttribute(ircn_fused,
                         cudaFuncAttributeMaxDynamicSharedMemorySize, STAGE_BYTES);

    init_kernel<<<1, 256>>>();
    ircn_fused<<<nPlanes, NTHREADS, STAGE_BYTES>>>(
        in, gRow, bRow, gCol, bCol, gIns, bIns, out, C, nPlanes);
}

// round 15
// speedup vs baseline: 1.1802x; 1.1676x over previous
#include <cuda_runtime.h>
#include <math.h>

#define HH 512
#define WW 512
#define HWSZ (HH * WW)
#define NTHREADS 512
#define NWARPS 16
#define EPSV 1e-8f
#define STAGE_ROWS 48
#define STAGE_BYTES (STAGE_ROWS * WW * 4)   // 96 KB dynamic smem

__global__ __launch_bounds__(NTHREADS, 2) void ircn_kernel(
    const float* __restrict__ in,
    const float* __restrict__ gRow_p, const float* __restrict__ bRow_p,
    const float* __restrict__ gCol_p, const float* __restrict__ bCol_p,
    const float* __restrict__ gIns_p, const float* __restrict__ bIns_p,
    float* __restrict__ out, int C)
{
    extern __shared__ __align__(16) float4 stage4[];   // STAGE_ROWS x 128 float4

    __shared__ __align__(16) float rowS[HH];
    __shared__ __align__(16) float rowSS[HH];
    __shared__ __align__(16) float colS[WW];
    __shared__ __align__(16) float colSS[WW];
    __shared__ float warpRed[NWARPS * 2];
    __shared__ float sIns[2];  // mean, inv

    const int plane = blockIdx.x;      // b*C + c
    const int c = plane % C;
    const int b = plane / C;
    const float* __restrict__ p = in + (size_t)plane * HWSZ;

    const int tid = threadIdx.x;
    const int lane = tid & 31;
    const int wid = tid >> 5;

    // init column accumulators (tid < 512 == WW)
    colS[tid] = 0.f;
    colSS[tid] = 0.f;
    __syncthreads();

    // ---------------- Phase A: stats (forward stream); stage head rows in smem ----
    // Staged rows are served from smem in phase B and never re-read from L2, so
    // load them evict-first (__ldcs) to keep L2 capacity for the unstaged tail.
    float cs[16], css[16];
#pragma unroll
    for (int i = 0; i < 16; i++) { cs[i] = 0.f; css[i] = 0.f; }

    for (int r = wid; r < HH; r += NWARPS) {
        const float4* rp = (const float4*)(p + (size_t)r * WW);
        float4 v[4];
        if (r < STAGE_ROWS) {
#pragma unroll
            for (int k = 0; k < 4; k++) v[k] = __ldcs(&rp[k * 32 + lane]);
#pragma unroll
            for (int k = 0; k < 4; k++) stage4[r * 128 + k * 32 + lane] = v[k];
        } else {
#pragma unroll
            for (int k = 0; k < 4; k++) v[k] = __ldcg(&rp[k * 32 + lane]);
        }

        float s = 0.f, ss = 0.f;
#pragma unroll
        for (int k = 0; k < 4; k++) {
            s += (v[k].x + v[k].y) + (v[k].z + v[k].w);
            ss += v[k].x * v[k].x + v[k].y * v[k].y + v[k].z * v[k].z + v[k].w * v[k].w;
            cs[k * 4 + 0] += v[k].x;  css[k * 4 + 0] += v[k].x * v[k].x;
            cs[k * 4 + 1] += v[k].y;  css[k * 4 + 1] += v[k].y * v[k].y;
            cs[k * 4 + 2] += v[k].z;  css[k * 4 + 2] += v[k].z * v[k].z;
            cs[k * 4 + 3] += v[k].w;  css[k * 4 + 3] += v[k].w * v[k].w;
        }
#pragma unroll
        for (int o = 16; o > 0; o >>= 1) {
            s += __shfl_xor_sync(0xffffffffu, s, o);
            ss += __shfl_xor_sync(0xffffffffu, ss, o);
        }
        if (lane == 0) { rowS[r] = s; rowSS[r] = ss; }
    }

    // flush per-lane column partials (16 fixed columns per lane)
#pragma unroll
    for (int k = 0; k < 4; k++) {
        int cbase = (k * 32 + lane) * 4;
#pragma unroll
        for (int j = 0; j < 4; j++) {
            atomicAdd(&colS[cbase + j], cs[k * 4 + j]);
            atomicAdd(&colSS[cbase + j], css[k * 4 + j]);
        }
    }
    __syncthreads();

    // plane (instance) reduction from row sums
    {
        float s = rowS[tid], ss = rowSS[tid];
#pragma unroll
        for (int o = 16; o > 0; o >>= 1) {
            s += __shfl_xor_sync(0xffffffffu, s, o);
            ss += __shfl_xor_sync(0xffffffffu, ss, o);
        }
        if (lane == 0) { warpRed[wid] = s; warpRed[NWARPS + wid] = ss; }
    }
    __syncthreads();
    if (tid == 0) {
        float s = 0.f, ss = 0.f;
        for (int i = 0; i < NWARPS; i++) { s += warpRed[i]; ss += warpRed[NWARPS + i]; }
        float m = s * (1.f / HWSZ);
        float v = fmaxf(ss * (1.f / HWSZ) - m * m, 0.f);
        sIns[0] = m;
        sIns[1] = 1.f / (sqrtf(v + EPSV) + EPSV);
    }

    // convert row/col raw sums -> mean & inv (thread t touches only index t; the
    // plane reduce above already consumed rowS[tid]/rowSS[tid])
    {
        float m = rowS[tid] * (1.f / WW);
        float v = fmaxf(rowSS[tid] * (1.f / WW) - m * m, 0.f);
        rowS[tid] = m;
        rowSS[tid] = 1.f / (sqrtf(v + EPSV) + EPSV);

        float mc = colS[tid] * (1.f / HH);
        float vc = fmaxf(colSS[tid] * (1.f / HH) - mc * mc, 0.f);
        colS[tid] = mc;
        colSS[tid] = 1.f / (sqrtf(vc + EPSV) + EPSV);
    }
    __syncthreads();

    // ---------------- Phase B: normalize & write (REVERSE stream) ----------------
    // Tail of the plane is the most-recently-cached in L2 after phase A, so read
    // back-to-front (LIFO order matches LRU retention). Head rows come from smem.
    const float gRow = gRow_p[c], bRow = bRow_p[c];
    const float gCol = gCol_p[c], bCol = bCol_p[c];
    const float gIns = gIns_p[c], bIns = bIns_p[c];
    const float insM = sIns[0], insI = sIns[1];

    const size_t outBase = (size_t)b * 3 * C * HWSZ;
    float* __restrict__ oI = out + outBase + (size_t)c * HWSZ;
    float* __restrict__ oR = out + outBase + (size_t)(C + c) * HWSZ;
    float* __restrict__ oC = out + outBase + (size_t)(2 * C + c) * HWSZ;

    const float4* colM4 = (const float4*)colS;
    const float4* colI4 = (const float4*)colSS;

    for (int r = (HH - 1) - wid; r >= 0; r -= NWARPS) {
        const float4* rp = (const float4*)(p + (size_t)r * WW);
        float4* oIp = (float4*)(oI + (size_t)r * WW);
        float4* oRp = (float4*)(oR + (size_t)r * WW);
        float4* oCp = (float4*)(oC + (size_t)r * WW);
        const float rm = rowS[r];
        const float ri = rowSS[r];
        const bool staged = (r < STAGE_ROWS);
#pragma unroll
        for (int k = 3; k >= 0; k--) {
            const int idx = k * 32 + lane;
            float4 v = staged ? stage4[r * 128 + idx] : __ldcs(&rp[idx]);
            float4 cm = colM4[idx];
            float4 ci = colI4[idx];
            float4 o;
            // instance norm
            o.x = gIns * (v.x - insM) * insI + bIns;
            o.y = gIns * (v.y - insM) * insI + bIns;
            o.z = gIns * (v.z - insM) * insI + bIns;
            o.w = gIns * (v.w - insM) * insI + bIns;
            __stcs(&oIp[idx], o);
            // row norm
            o.x = gRow * (v.x - rm) * ri + bRow;
            o.y = gRow * (v.y - rm) * ri + bRow;
            o.z = gRow * (v.z - rm) * ri + bRow;
            o.w = gRow * (v.w - rm) * ri + bRow;
            __stcs(&oRp[idx], o);
            // col norm
            o.x = gCol * (v.x - cm.x) * ci.x + bCol;
            o.y = gCol * (v.y - cm.y) * ci.y + bCol;
            o.z = gCol * (v.z - cm.z) * ci.z + bCol;
            o.w = gCol * (v.w - cm.w) * ci.w + bCol;
            __stcs(&oCp[idx], o);
        }
    }
}

extern "C" void kernel_launch(void* const* d_in, const int* in_sizes, int n_in,
                              void* d_out, int out_size) {
    const float* in = (const float*)d_in[0];
    const float* gRow = (const float*)d_in[1];
    const float* bRow = (const float*)d_in[2];
    const float* gCol = (const float*)d_in[3];
    const float* bCol = (const float*)d_in[4];
    const float* gIns = (const float*)d_in[5];
    const float* bIns = (const float*)d_in[6];
    float* out = (float*)d_out;

    const int C = in_sizes[1];                  // 128
    const int nPlanes = in_sizes[0] / HWSZ;     // B*C = 256

    cudaFuncSetAttribute(ircn_kernel,
                         cudaFuncAttributeMaxDynamicSharedMemorySize, STAGE_BYTES);

    ircn_kernel<<<nPlanes, NTHREADS, STAGE_BYTES>>>(
        in, gRow, bRow, gCol, bCol, gIns, bIns, out, C);
}